// round 15
// baseline (speedup 1.0000x reference)
#include <cuda_runtime.h>
#include <math.h>
#include <stdint.h>

#define BB    64
#define TTT   512
#define FIN_  256
#define HH    1024
#define OUTD  64
#define GRID  128
#define NTHR  512
#define KSLAB 32
#define SST   72            // smem row stride (mod 32 == 8 -> conflict-free)
#define HB    (HH*BB)       // 65536

// ---------------- static device scratch ------------------------------------
__device__ __align__(16) float g_xe[(size_t)TTT*HB];      // exact x@We_in, [t][n][m]
__device__ __align__(16) float g_Wcat[2048*4096];         // [W_ih;W_hh] tf32-rounded
__device__ __align__(16) float g_Weh[HH*HH];              // rounded weight copies
__device__ __align__(16) float g_Weo[HH*HH];
__device__ __align__(16) float g_Woi[HH*HH];
__device__ __align__(16) float g_Woh[HH*HH];
__device__ __align__(16) float g_Woo[HH*OUTD];
__device__ __align__(16) float g_Wey[128*HH];             // We_in y-rows, rounded
__device__ __align__(16) float g_Wfused[HH*HH];           // Woo @ (Wey_y+Wey_yp), rounded
__device__ __align__(16) float g_beff[HH];                // b_e_in + bo@Wsum (fp32)
__device__ __align__(16) float g_rh[2*HB];                // rows 1024-2047: h (rounded)
__device__ __align__(16) float g_hr[HB];                  // relu(h) rounded
__device__ __align__(16) float g_c[HB];                   // exact fp32 cell state
// RED accumulator planes (pre-zeroed; producers red.add, consumers read, then zeroed)
__device__ __align__(16) float g_accE2[HB];
__device__ __align__(16) float g_accE [HB];
__device__ __align__(16) float g_accG [4*HB];
__device__ __align__(16) float g_accD1[HB];
__device__ __align__(16) float g_accD2[HB];
__device__ __align__(16) float g_accE1[HB];
__device__ __align__(16) float g_accY [OUTD*BB];
__device__ __align__(16) float g_y2[2*OUTD*BB];           // prologue [y1;y0], [j][b]
__device__ unsigned g_bar;

__device__ __forceinline__ float sigm(float v){ return 1.0f/(1.0f + expf(-v)); }

__device__ __forceinline__ float tf32r(float v){
    uint32_t u; asm("cvt.rna.tf32.f32 %0, %1;" : "=r"(u) : "f"(v));
    return __uint_as_float(u);
}

__device__ __forceinline__ void redadd(float* p, float v){
    asm volatile("red.global.add.f32 [%0], %1;" :: "l"(p), "f"(v) : "memory");
}

#define CP_ASYNC16(dst, src) \
    asm volatile("cp.async.cg.shared.global [%0], [%1], 16;" :: "r"(dst), "l"(src) : "memory")
#define CP_COMMIT  asm volatile("cp.async.commit_group;" ::: "memory")
#define CP_WAIT(n) asm volatile("cp.async.wait_group %0;" :: "n"(n) : "memory")

__device__ __forceinline__ void mma_tf32(float c[4], const uint32_t a[4], const uint32_t b[2]){
    asm volatile("mma.sync.aligned.m16n8k8.row.col.f32.tf32.tf32.f32 "
        "{%0,%1,%2,%3}, {%4,%5,%6,%7}, {%8,%9}, {%0,%1,%2,%3};"
        : "+f"(c[0]), "+f"(c[1]), "+f"(c[2]), "+f"(c[3])
        : "r"(a[0]), "r"(a[1]), "r"(a[2]), "r"(a[3]), "r"(b[0]), "r"(b[1]));
}

// ---------------- grid barrier: combined + split arrive/wait -----------------
__device__ __forceinline__ void bar_arrive(int tid){
    __syncthreads();
    if (tid == 0){
        __threadfence();                 // release all CTA writes (incl. REDs)
        atomicAdd(&g_bar, 1u);
    }
}
__device__ __forceinline__ void bar_wait(int tid, unsigned &target){
    if (tid == 0){
        while (*(volatile unsigned*)&g_bar < target) { }
        __threadfence();                 // acquire
    }
    __syncthreads();
    target += GRID;
}
__device__ __forceinline__ void grid_barrier(int tid, unsigned &target){
    bar_arrive(tid);
    bar_wait(tid, target);
}

// ---------------- 16-warp mma core (warp = m16 x n16) + RED epilogue ---------
__device__ __forceinline__ void mma_body(
    float acc[2][4], const float* sA, const float* sW, int cur,
    int wm, int wn, int fr, int fc, bool live)
{
#pragma unroll
    for (int kq = 0; kq < KSLAB/8; kq++){
        const float* Ak = sA + cur + kq*8*SST;
        const float* Wk = sW + cur + kq*8*SST;
        uint32_t af[4], bf[2][2];
        const int m0 = wm*16;
        af[0] = __float_as_uint(Ak[ fc   *SST + m0 + fr    ]);
        af[1] = __float_as_uint(Ak[ fc   *SST + m0 + fr + 8]);
        af[2] = __float_as_uint(Ak[(fc+4)*SST + m0 + fr    ]);
        af[3] = __float_as_uint(Ak[(fc+4)*SST + m0 + fr + 8]);
#pragma unroll
        for (int nq = 0; nq < 2; nq++){
            const int n0 = wn*16 + nq*8;
            bf[nq][0] = __float_as_uint(Wk[ fc   *SST + n0 + fr]);
            bf[nq][1] = __float_as_uint(Wk[(fc+4)*SST + n0 + fr]);
        }
        if (live){
            mma_tf32(acc[0], af, bf[0]);
            mma_tf32(acc[1], af, bf[1]);
        }
    }
}

__device__ __forceinline__ void red_epilogue(
    float acc[2][4], float* outAcc, int wm, int wn, int fr, int fc, int m_eff)
{
    const int m0 = wm*16;
    if (m0 >= m_eff) return;
#pragma unroll
    for (int nq = 0; nq < 2; nq++){
        const int col = wn*16 + nq*8 + 2*fc;
        redadd(outAcc + (size_t)col*64     + m0 + fr,     acc[nq][0]);
        redadd(outAcc + (size_t)(col+1)*64 + m0 + fr,     acc[nq][1]);
        redadd(outAcc + (size_t)col*64     + m0 + fr + 8, acc[nq][2]);
        redadd(outAcc + (size_t)(col+1)*64 + m0 + fr + 8, acc[nq][3]);
    }
}

// ---------------- plain-A GEMM (A via cp.async), RED output ------------------
__device__ __noinline__ void gemm_red(
    const float* __restrict__ A, const float* __restrict__ W,
    int ldw, int kc, float* __restrict__ outAcc, int m_eff,
    float* sA, float* sW, int tid)
{
    const int lane = tid & 31;
    const int wid  = tid >> 5;
    const int wm = wid & 3, wn = wid >> 2;
    const int fr = lane >> 2, fc = lane & 3;
    const int r  = tid >> 4;              // 0..31
    const int c4 = (tid & 15) << 2;
    const unsigned la = (unsigned)((r*SST + c4) * 4);
    const unsigned aB = (unsigned)__cvta_generic_to_shared(sA);
    const unsigned wB = (unsigned)__cvta_generic_to_shared(sW);
    const int nslab = kc >> 5;
    const bool live = (wm*16) < m_eff;

    float acc[2][4];
#pragma unroll
    for (int j = 0; j < 2; j++)
#pragma unroll
        for (int q = 0; q < 4; q++) acc[j][q] = 0.f;

    {
        CP_ASYNC16(aB + la, A + (size_t)r*64 + c4);
        CP_ASYNC16(wB + la, W + (size_t)r*ldw + c4);
        CP_COMMIT;
    }
    for (int s = 0; s < nslab; s++){
        const int cur = (s & 1) ? KSLAB*SST : 0;
        if (s + 1 < nslab){
            const unsigned nxt = ((s+1) & 1) ? (unsigned)(KSLAB*SST*4) : 0u;
            CP_ASYNC16(aB + nxt + la, A + (size_t)((s+1)*KSLAB + r)*64 + c4);
            CP_ASYNC16(wB + nxt + la, W + (size_t)((s+1)*KSLAB + r)*ldw + c4);
            CP_COMMIT;
            CP_WAIT(1);
        } else { CP_WAIT(0); }
        __syncthreads();
        mma_body(acc, sA, sW, cur, wm, wn, fr, fc, live);
        __syncthreads();
    }
    red_epilogue(acc, outAcc, wm, wn, fr, fc, m_eff);
}

// ---------------- math-A GEMM: A = tf32r(relu(acc (+xe) + bias[k])) ----------
template<bool HASXE>
__device__ __noinline__ void gemm_red_mA(
    const float* __restrict__ accP, const float* __restrict__ xe,
    const float* __restrict__ bias,
    const float* __restrict__ W, int ldw, int kc,
    float* __restrict__ outAcc, int m_eff,
    float* sA, float* sW, int tid)
{
    const int lane = tid & 31;
    const int wid  = tid >> 5;
    const int wm = wid & 3, wn = wid >> 2;
    const int fr = lane >> 2, fc = lane & 3;
    const int r  = tid >> 4;
    const int c4 = (tid & 15) << 2;
    const unsigned la = (unsigned)((r*SST + c4) * 4);
    const unsigned wB = (unsigned)__cvta_generic_to_shared(sW);
    const int nslab = kc >> 5;
    const bool live = (wm*16) < m_eff;

    float acc[2][4];
#pragma unroll
    for (int j = 0; j < 2; j++)
#pragma unroll
        for (int q = 0; q < 4; q++) acc[j][q] = 0.f;

    float4 a0, x0; float b0;
    auto loadA = [&](int s){
        size_t base = (size_t)(s*KSLAB + r)*64 + c4;
        a0 = *(const float4*)(accP + base);
        if (HASXE) x0 = *(const float4*)(xe + base);
        b0 = bias[s*KSLAB + r];
    };
    auto stsA = [&](int s){
        float* dst = sA + ((s & 1) ? KSLAB*SST : 0);
        float4 v0;
        v0.x = tf32r(fmaxf(a0.x + (HASXE ? x0.x : 0.f) + b0, 0.f));
        v0.y = tf32r(fmaxf(a0.y + (HASXE ? x0.y : 0.f) + b0, 0.f));
        v0.z = tf32r(fmaxf(a0.z + (HASXE ? x0.z : 0.f) + b0, 0.f));
        v0.w = tf32r(fmaxf(a0.w + (HASXE ? x0.w : 0.f) + b0, 0.f));
        *(float4*)(dst + r*SST + c4) = v0;
    };
    auto cpW = [&](int s){
        const unsigned off = (s & 1) ? (unsigned)(KSLAB*SST*4) : 0u;
        CP_ASYNC16(wB + off + la, W + (size_t)(s*KSLAB + r)*ldw + c4);
        CP_COMMIT;
    };

    loadA(0);
    cpW(0);
    for (int s = 0; s < nslab; s++){
        const int cur = (s & 1) ? KSLAB*SST : 0;
        stsA(s);
        if (s + 1 < nslab){
            cpW(s + 1);
            loadA(s + 1);
            CP_WAIT(1);
        } else { CP_WAIT(0); }
        __syncthreads();
        mma_body(acc, sA, sW, cur, wm, wn, fr, fc, live);
        __syncthreads();
    }
    red_epilogue(acc, outAcc, wm, wn, fr, fc, m_eff);
}

// ---------------- init A ------------------------------------------------------
__global__ void init_misc(const float* __restrict__ y0,
                          const float* __restrict__ y1,
                          const float* __restrict__ W_e_in,
                          const float* __restrict__ W_e_h,
                          const float* __restrict__ W_e_out,
                          const float* __restrict__ W_ih,
                          const float* __restrict__ W_hh,
                          const float* __restrict__ W_o_in,
                          const float* __restrict__ W_o_h,
                          const float* __restrict__ W_o_out){
    int i = blockIdx.x * blockDim.x + threadIdx.x;
    int n = gridDim.x * blockDim.x;
    if (i == 0) g_bar = 0u;
    for (int idx = i; idx < 2*HB; idx += n) g_rh[idx] = 0.f;
    for (int idx = i; idx < HB; idx += n){
        g_c[idx] = 0.f; g_hr[idx] = 0.f;
        g_accE2[idx] = 0.f; g_accE[idx] = 0.f;
        g_accD1[idx] = 0.f; g_accD2[idx] = 0.f; g_accE1[idx] = 0.f;
    }
    for (int idx = i; idx < 4*HB; idx += n) g_accG[idx] = 0.f;
    for (int idx = i; idx < OUTD*BB; idx += n){
        g_accY[idx] = 0.f;
        int j = idx >> 6, b = idx & 63;
        g_y2[idx]           = tf32r(y1[b*OUTD + j]);
        g_y2[OUTD*BB + idx] = tf32r(y0[b*OUTD + j]);
    }
    for (int idx = i; idx < HH*HH; idx += n){
        g_Weh[idx] = tf32r(W_e_h[idx]);
        g_Weo[idx] = tf32r(W_e_out[idx]);
        g_Woi[idx] = tf32r(W_o_in[idx]);
        g_Woh[idx] = tf32r(W_o_h[idx]);
    }
    for (int idx = i; idx < HH*OUTD; idx += n) g_Woo[idx] = tf32r(W_o_out[idx]);
    for (int idx = i; idx < 128*HH; idx += n)
        g_Wey[idx] = tf32r(W_e_in[(size_t)256*HH + idx]);
    for (int idx = i; idx < 1024*4096; idx += n){
        g_Wcat[idx]                     = tf32r(W_ih[idx]);
        g_Wcat[(size_t)1024*4096 + idx] = tf32r(W_hh[idx]);
    }
}

// ---------------- init B: xe[t] = x_t @ W_e_in[0:256]  (fp32 exact) ----------
__global__ void init_xe(const float* __restrict__ x,
                        const float* __restrict__ W_e_in){
    __shared__ __align__(16) float As[16*64];
    __shared__ __align__(16) float Ws[16*64];
    const int tid = threadIdx.x;
    const int t  = blockIdx.x >> 4;
    const int nt = blockIdx.x & 15;
    const int tx = tid & 15, ty = tid >> 4;

    float acc[4][4] = {{0,0,0,0},{0,0,0,0},{0,0,0,0},{0,0,0,0}};
    for (int kb = 0; kb < FIN_; kb += 16){
        {
            int m  = tid >> 2;
            int kq = (tid & 3) << 2;
            float4 v = *(const float4*)(x + ((size_t)m*TTT + t)*FIN_ + kb + kq);
            As[(kq+0)*64 + m] = v.x; As[(kq+1)*64 + m] = v.y;
            As[(kq+2)*64 + m] = v.z; As[(kq+3)*64 + m] = v.w;
        }
        {
            int k  = tid >> 4;
            int n4 = (tid & 15) << 2;
            *(float4*)&Ws[k*64 + n4] = *(const float4*)(W_e_in + (size_t)(kb + k)*HH + nt*64 + n4);
        }
        __syncthreads();
#pragma unroll
        for (int k = 0; k < 16; k++){
            float4 a = *(const float4*)&As[k*64 + (ty << 2)];
            float4 w = *(const float4*)&Ws[k*64 + (tx << 2)];
            acc[0][0] = fmaf(a.x, w.x, acc[0][0]); acc[0][1] = fmaf(a.x, w.y, acc[0][1]);
            acc[0][2] = fmaf(a.x, w.z, acc[0][2]); acc[0][3] = fmaf(a.x, w.w, acc[0][3]);
            acc[1][0] = fmaf(a.y, w.x, acc[1][0]); acc[1][1] = fmaf(a.y, w.y, acc[1][1]);
            acc[1][2] = fmaf(a.y, w.z, acc[1][2]); acc[1][3] = fmaf(a.y, w.w, acc[1][3]);
            acc[2][0] = fmaf(a.z, w.x, acc[2][0]); acc[2][1] = fmaf(a.z, w.y, acc[2][1]);
            acc[2][2] = fmaf(a.z, w.z, acc[2][2]); acc[2][3] = fmaf(a.z, w.w, acc[2][3]);
            acc[3][0] = fmaf(a.w, w.x, acc[3][0]); acc[3][1] = fmaf(a.w, w.y, acc[3][1]);
            acc[3][2] = fmaf(a.w, w.z, acc[3][2]); acc[3][3] = fmaf(a.w, w.w, acc[3][3]);
        }
        __syncthreads();
    }
    const int m0 = ty << 2;
#pragma unroll
    for (int j = 0; j < 4; j++){
        int ng = nt*64 + (tx << 2) + j;
        *(float4*)(g_xe + (size_t)t*HB + (size_t)ng*64 + m0) =
            make_float4(acc[0][j], acc[1][j], acc[2][j], acc[3][j]);
    }
}

// ---------------- init C: Wfused = Woo @ (Wey_y + Wey_yp); beff --------------
__global__ void init_wf(const float* __restrict__ W_e_in,
                        const float* __restrict__ W_o_out,
                        const float* __restrict__ b_e_in,
                        const float* __restrict__ b_o_out){
    const int kt = blockIdx.x >> 4;
    const int nt = blockIdx.x & 15;
    const int tid = threadIdx.x;
    const int kr = tid >> 2;
    const int n0 = (tid & 3) * 16;

    const int k = kt*64 + kr;
    float acc[16];
#pragma unroll
    for (int q = 0; q < 16; q++) acc[q] = 0.f;
    for (int j = 0; j < 64; j++){
        float woo = W_o_out[(size_t)k*OUTD + j];
        const float* wy = W_e_in + (size_t)(256 + j)*HH + nt*64 + n0;
        const float* wp = W_e_in + (size_t)(320 + j)*HH + nt*64 + n0;
#pragma unroll
        for (int q = 0; q < 16; q++)
            acc[q] = fmaf(woo, wy[q] + wp[q], acc[q]);
    }
#pragma unroll
    for (int q = 0; q < 16; q++)
        g_Wfused[(size_t)k*HH + nt*64 + n0 + q] = tf32r(acc[q]);

    if (kt == 0 && tid < 64){
        int nn = nt*64 + tid;
        float s = b_e_in[nn];
        for (int j = 0; j < 64; j++)
            s = fmaf(b_o_out[j],
                     W_e_in[(size_t)(256 + j)*HH + nn] + W_e_in[(size_t)(320 + j)*HH + nn], s);
        g_beff[nn] = s;
    }
}

// ---------------- persistent RNN kernel -------------------------------------
__global__ void __launch_bounds__(NTHR, 1)
rnn_kernel(const int* __restrict__ x_len,
           const float* __restrict__ b_e_in,  const float* __restrict__ b_e_h,
           const float* __restrict__ b_e_out,
           const float* __restrict__ b_ih,    const float* __restrict__ b_hh,
           const float* __restrict__ b_o_in,  const float* __restrict__ b_o_h,
           const float* __restrict__ b_o_out,
           float* __restrict__ out)
{
    __shared__ __align__(16) float sA[2*KSLAB*SST];   // 18KB
    __shared__ __align__(16) float sW[2*KSLAB*SST];   // 18KB
    __shared__ int s_meff[TTT];
    __shared__ int s_xlen[BB];

    const int tid  = threadIdx.x;
    const int bid  = blockIdx.x;
    const int gtid = bid * NTHR + tid;
    unsigned target = GRID;

    float* __restrict__ ys_out   = out;
    float* __restrict__ skip_out = out + (size_t)BB*TTT*OUTD;

    if (tid < BB) s_xlen[tid] = x_len[tid];
    __syncthreads();
    for (int t = tid; t < TTT; t += NTHR){
        int c = 0;
#pragma unroll
        for (int m = 0; m < BB; m++) c += (s_xlen[m] > t) ? 1 : 0;
        s_meff[t] = c;
    }
    __syncthreads();

    // ==== prologue: accE1 += [y1;y0]@Wey  (32 jobs, kc=64) ====
    if (bid < 32){
        int nt = bid & 15, ks = bid >> 4;
        gemm_red(g_y2 + (size_t)ks*64*BB, g_Wey + (size_t)(ks*64)*HH + nt*64,
                 HH, 64, g_accE1 + (size_t)nt*4096, 64, sA, sW, tid);
    }
    grid_barrier(tid, target);

    for (int t = 0; t < TTT; t++){
        const int me = s_meff[t];

        // ---- P1: e1 = f(accE1 + xe[t] + bias) staged; @ W_e_h -> RED accE2.
        //          16nt x 8ks, kc=128, all 128 CTAs.
        {
            int nt = bid & 15, ks = bid >> 4;
            const float* bias = (t == 0) ? b_e_in : g_beff;
            gemm_red_mA<true>(g_accE1 + (size_t)ks*128*64,
                              g_xe + (size_t)t*HB + (size_t)ks*128*64,
                              bias + ks*128,
                              g_Weh + (size_t)(ks*128)*HH + nt*64, HH, 128,
                              g_accE2 + (size_t)nt*4096, me, sA, sW, tid);
        }
        grid_barrier(tid, target);

        // ---- P3: e2 = f(accE2 + b_e_h) staged; @ W_e_out -> RED accE.
        //          Post-arrive: zero accE1 (consumed P11, 4 bars later);
        //                       y-store + zero accY (accY: P11 REDs).
        {
            int nt = bid & 15, ks = bid >> 4;
            gemm_red_mA<false>(g_accE2 + (size_t)ks*128*64, (const float*)0,
                               b_e_h + ks*128,
                               g_Weo + (size_t)(ks*128)*HH + nt*64, HH, 128,
                               g_accE + (size_t)nt*4096, me, sA, sW, tid);
        }
        bar_arrive(tid);
        for (int idx = gtid*4; idx < HB; idx += GRID*NTHR*4)
            *(float4*)(g_accE1 + idx) = make_float4(0.f,0.f,0.f,0.f);
        if (t > 0){
            const int mep = s_meff[t-1];
            for (int idx = gtid; idx < OUTD*BB; idx += GRID*NTHR){
                float yv = g_accY[idx] + b_o_out[idx >> 6];
                int nn = idx >> 6, m = idx & 63;
                ys_out[((size_t)m*TTT + (t-1))*OUTD + nn] = (m < mep) ? yv : 0.f;
                g_accY[idx] = 0.f;
            }
        }
        bar_wait(tid, target);

        // ---- P5: gates = [r;h] @ W_cat (64nt x 2ks, kc=1024) -> RED accG.
        //          ks==0: r = f(accE + b_e_out) staged; ks==1: h from g_rh.
        //          Post-arrive: zero accE2 (consumed P1 next step, 3 bars).
        {
            int nt = bid & 63, ks = bid >> 6;
            if (ks == 0)
                gemm_red_mA<false>(g_accE, (const float*)0, b_e_out,
                                   g_Wcat + nt*64, 4096, 1024,
                                   g_accG + (size_t)nt*4096, me, sA, sW, tid);
            else
                gemm_red(g_rh + (size_t)HB,
                         g_Wcat + (size_t)1024*4096 + nt*64, 4096, 1024,
                         g_accG + (size_t)nt*4096, me, sA, sW, tid);
        }
        bar_arrive(tid);
        for (int idx = gtid*4; idx < HB; idx += GRID*NTHR*4)
            *(float4*)(g_accE2 + idx) = make_float4(0.f,0.f,0.f,0.f);
        bar_wait(tid, target);

        // ---- P6: LSTM pointwise (+ accD1 zero) before arrive;
        //          skip store + accE/accG/accD2 zero after arrive.
        for (int idx = gtid; idx < HB; idx += GRID*NTHR){
            int j = idx >> 6, m = idx & 63;
            size_t o0 = (size_t)j*64 + m;
            float ig = g_accG[o0              ] + b_ih[j     ] + b_hh[j     ];
            float fg = g_accG[o0 +     (size_t)HB] + b_ih[j+1024] + b_hh[j+1024];
            float gg = g_accG[o0 + 2*(size_t)HB] + b_ih[j+2048] + b_hh[j+2048];
            float og = g_accG[o0 + 3*(size_t)HB] + b_ih[j+3072] + b_hh[j+3072];
            float cn = sigm(fg)*g_c[idx] + sigm(ig)*tanhf(gg);
            float hn = sigm(og)*tanhf(cn);
            g_c[idx] = cn;
            float ht = tf32r(hn);
            g_rh[HB + idx] = ht;
            g_hr[idx]      = fmaxf(ht, 0.f);
            g_accD1[idx]   = 0.f;           // consumed next phase -> before arrive
        }
        bar_arrive(tid);
        for (int idx = gtid; idx < HB; idx += GRID*NTHR){
            int j = idx >> 6, m = idx & 63;
            float e = g_accE[idx] + b_e_out[j];
            skip_out[((size_t)m*TTT + t)*HH + j] = (m < me) ? e : 0.f;
            g_accE[idx]  = 0.f;             // consumed P3 next step
            g_accD2[idx] = 0.f;             // consumed P9 (2 bars later)
            size_t o0 = (size_t)j*64 + m;
            g_accG[o0              ] = 0.f; // consumed P5 next step
            g_accG[o0 +     (size_t)HB] = 0.f;
            g_accG[o0 + 2*(size_t)HB] = 0.f;
            g_accG[o0 + 3*(size_t)HB] = 0.f;
        }
        bar_wait(tid, target);

        // ---- P7: d1 = relu(h) @ W_o_in -> RED accD1.  16nt x 8ks, kc=128.
        {
            int nt = bid & 15, ks = bid >> 4;
            gemm_red(g_hr + (size_t)ks*128*BB,
                     g_Woi + (size_t)(ks*128)*HH + nt*64, HH, 128,
                     g_accD1 + (size_t)nt*4096, me, sA, sW, tid);
        }
        grid_barrier(tid, target);

        // ---- P9: d1 = f(accD1 + b_o_in) staged; @ W_o_h -> RED accD2.
        {
            int nt = bid & 15, ks = bid >> 4;
            gemm_red_mA<false>(g_accD1 + (size_t)ks*128*64, (const float*)0,
                               b_o_in + ks*128,
                               g_Woh + (size_t)(ks*128)*HH + nt*64, HH, 128,
                               g_accD2 + (size_t)nt*4096, me, sA, sW, tid);
        }
        grid_barrier(tid, target);

        // ---- P11: d2 = f(accD2 + b_o_h) staged;
        //           bid<64: @ Wfused (16nt x 4ks, kc=256) -> RED accE1
        //           bid 64-71: @ Woo (kc=128, 8ks) -> RED accY
        if (bid < 64){
            int nt = bid & 15, ks = bid >> 4;
            gemm_red_mA<false>(g_accD2 + (size_t)ks*256*64, (const float*)0,
                               b_o_h + ks*256,
                               g_Wfused + (size_t)(ks*256)*HH + nt*64, HH, 256,
                               g_accE1 + (size_t)nt*4096, me, sA, sW, tid);
        } else if (bid < 72){
            int ks = bid - 64;
            gemm_red_mA<false>(g_accD2 + (size_t)ks*128*64, (const float*)0,
                               b_o_h + ks*128,
                               g_Woo + (size_t)(ks*128)*OUTD, OUTD, 128,
                               g_accY, me, sA, sW, tid);
        }
        grid_barrier(tid, target);
    }

    // ==== epilogue: store y(T-1) ====
    {
        const int mep = s_meff[TTT-1];
        for (int idx = gtid; idx < OUTD*BB; idx += GRID*NTHR){
            float yv = g_accY[idx] + b_o_out[idx >> 6];
            int nn = idx >> 6, m = idx & 63;
            ys_out[((size_t)m*TTT + (TTT-1))*OUTD + nn] = (m < mep) ? yv : 0.f;
        }
    }
}

// ---------------- launch -----------------------------------------------------
extern "C" void kernel_launch(void* const* d_in, const int* in_sizes, int n_in,
                              void* d_out, int out_size)
{
    (void)in_sizes; (void)n_in; (void)out_size;
    const float* x       = (const float*)d_in[0];
    const int*   x_len   = (const int*)  d_in[1];
    const float* y_0     = (const float*)d_in[2];
    const float* y_1     = (const float*)d_in[3];
    const float* W_e_in  = (const float*)d_in[4];
    const float* b_e_in  = (const float*)d_in[5];
    const float* W_e_h   = (const float*)d_in[6];
    const float* b_e_h   = (const float*)d_in[7];
    const float* W_e_out = (const float*)d_in[8];
    const float* b_e_out = (const float*)d_in[9];
    const float* W_ih    = (const float*)d_in[10];
    const float* W_hh    = (const float*)d_in[11];
    const float* b_ih    = (const float*)d_in[12];
    const float* b_hh    = (const float*)d_in[13];
    const float* W_o_in  = (const float*)d_in[14];
    const float* b_o_in  = (const float*)d_in[15];
    const float* W_o_h   = (const float*)d_in[16];
    const float* b_o_h   = (const float*)d_in[17];
    const float* W_o_out = (const float*)d_in[18];
    const float* b_o_out = (const float*)d_in[19];

    init_misc<<<1024, 256>>>(y_0, y_1, W_e_in, W_e_h, W_e_out,
                             W_ih, W_hh, W_o_in, W_o_h, W_o_out);
    init_xe<<<TTT*16, 256>>>(x, W_e_in);
    init_wf<<<256, 256>>>(W_e_in, W_o_out, b_e_in, b_o_out);
    rnn_kernel<<<GRID, NTHR>>>(x_len,
                               b_e_in, b_e_h, b_e_out,
                               b_ih, b_hh,
                               b_o_in, b_o_h, b_o_out,
                               (float*)d_out);
}

// round 17
// speedup vs baseline: 1.1503x; 1.1503x over previous
#include <cuda_runtime.h>
#include <math.h>
#include <stdint.h>

#define BB    64
#define TTT   512
#define FIN_  256
#define HH    1024
#define OUTD  64
#define GRID  256
#define NTHR  256
#define KSLAB 32
#define SST   72            // smem row stride (mod 32 == 8 -> conflict-free)
#define HB    (HH*BB)       // 65536

// ---------------- static device scratch ------------------------------------
__device__ __align__(16) float g_xe[(size_t)TTT*HB];      // exact x@We_in, [t][n][m]
__device__ __align__(16) float g_Wcat[2048*4096];         // [W_ih;W_hh] tf32-rounded
__device__ __align__(16) float g_Weh[HH*HH];              // rounded weight copies
__device__ __align__(16) float g_Weo[HH*HH];
__device__ __align__(16) float g_Woi[HH*HH];
__device__ __align__(16) float g_Woh[HH*HH];
__device__ __align__(16) float g_Woo[HH*OUTD];
__device__ __align__(16) float g_Wey[128*HH];             // We_in y-rows, rounded
__device__ __align__(16) float g_Wfused[HH*HH];           // Woo @ (Wey_y+Wey_yp), rounded
__device__ __align__(16) float g_beff[HH];                // b_e_in + bo@Wsum (fp32)
__device__ __align__(16) float g_rh[2*HB];                // rows 1024-2047: h (rounded)
__device__ __align__(16) float g_hr[HB];                  // relu(h) rounded
__device__ __align__(16) float g_c[HB];                   // exact fp32 cell state
// RED accumulator planes (pre-zeroed; producers red.add, consumers read, then zeroed)
__device__ __align__(16) float g_accE2[HB];
__device__ __align__(16) float g_accE [HB];
__device__ __align__(16) float g_accG [4*HB];
__device__ __align__(16) float g_accD1[HB];
__device__ __align__(16) float g_accD2[HB];
__device__ __align__(16) float g_accE1[HB];
__device__ __align__(16) float g_accY [OUTD*BB];
__device__ __align__(16) float g_y2[2*OUTD*BB];           // prologue [y1;y0], [j][b]
__device__ unsigned g_bar;

__device__ __forceinline__ float sigm(float v){ return 1.0f/(1.0f + expf(-v)); }

__device__ __forceinline__ float tf32r(float v){
    uint32_t u; asm("cvt.rna.tf32.f32 %0, %1;" : "=r"(u) : "f"(v));
    return __uint_as_float(u);
}

__device__ __forceinline__ void redadd(float* p, float v){
    asm volatile("red.global.add.f32 [%0], %1;" :: "l"(p), "f"(v) : "memory");
}

#define CP_ASYNC16(dst, src) \
    asm volatile("cp.async.cg.shared.global [%0], [%1], 16;" :: "r"(dst), "l"(src) : "memory")
#define CP_COMMIT  asm volatile("cp.async.commit_group;" ::: "memory")
#define CP_WAIT(n) asm volatile("cp.async.wait_group %0;" :: "n"(n) : "memory")

__device__ __forceinline__ void mma_tf32(float c[4], const uint32_t a[4], const uint32_t b[2]){
    asm volatile("mma.sync.aligned.m16n8k8.row.col.f32.tf32.tf32.f32 "
        "{%0,%1,%2,%3}, {%4,%5,%6,%7}, {%8,%9}, {%0,%1,%2,%3};"
        : "+f"(c[0]), "+f"(c[1]), "+f"(c[2]), "+f"(c[3])
        : "r"(a[0]), "r"(a[1]), "r"(a[2]), "r"(a[3]), "r"(b[0]), "r"(b[1]));
}

// ---------------- grid barrier: split arrive/wait ----------------------------
__device__ __forceinline__ void bar_arrive(int tid){
    __syncthreads();
    if (tid == 0){
        __threadfence();                 // release all CTA writes (incl. REDs)
        atomicAdd(&g_bar, 1u);
    }
}
__device__ __forceinline__ void bar_wait(int tid, unsigned &target){
    if (tid == 0){
        while (*(volatile unsigned*)&g_bar < target) { }
        __threadfence();                 // acquire
    }
    __syncthreads();
    target += GRID;
}
__device__ __forceinline__ void grid_barrier(int tid, unsigned &target){
    bar_arrive(tid);
    bar_wait(tid, target);
}

// ---------------- shared mma core + RED epilogue -----------------------------
__device__ __forceinline__ void mma_body(
    float acc[2][2][4], const float* sA, const float* sW, int cur,
    int wm, int wn, int fr, int fc, bool live0, bool live1)
{
#pragma unroll
    for (int kq = 0; kq < KSLAB/8; kq++){
        const float* Ak = sA + cur + kq*8*SST;
        const float* Wk = sW + cur + kq*8*SST;
        uint32_t af[2][4], bf[2][2];
#pragma unroll
        for (int mt = 0; mt < 2; mt++){
            const int m0 = wm*32 + mt*16;
            af[mt][0] = __float_as_uint(Ak[ fc   *SST + m0 + fr    ]);
            af[mt][1] = __float_as_uint(Ak[ fc   *SST + m0 + fr + 8]);
            af[mt][2] = __float_as_uint(Ak[(fc+4)*SST + m0 + fr    ]);
            af[mt][3] = __float_as_uint(Ak[(fc+4)*SST + m0 + fr + 8]);
        }
#pragma unroll
        for (int nq = 0; nq < 2; nq++){
            const int n0 = wn*16 + nq*8;
            bf[nq][0] = __float_as_uint(Wk[ fc   *SST + n0 + fr]);
            bf[nq][1] = __float_as_uint(Wk[(fc+4)*SST + n0 + fr]);
        }
        if (live0){ mma_tf32(acc[0][0], af[0], bf[0]);
                    mma_tf32(acc[0][1], af[0], bf[1]); }
        if (live1){ mma_tf32(acc[1][0], af[1], bf[0]);
                    mma_tf32(acc[1][1], af[1], bf[1]); }
    }
}

__device__ __forceinline__ void red_epilogue(
    float acc[2][2][4], float* outAcc, int wm, int wn, int fr, int fc, int m_eff)
{
#pragma unroll
    for (int mt = 0; mt < 2; mt++){
        const int m0 = wm*32 + mt*16;
        if (m0 >= m_eff) continue;
#pragma unroll
        for (int nq = 0; nq < 2; nq++){
            const int col = wn*16 + nq*8 + 2*fc;
            redadd(outAcc + (size_t)col*64     + m0 + fr,     acc[mt][nq][0]);
            redadd(outAcc + (size_t)(col+1)*64 + m0 + fr,     acc[mt][nq][1]);
            redadd(outAcc + (size_t)col*64     + m0 + fr + 8, acc[mt][nq][2]);
            redadd(outAcc + (size_t)(col+1)*64 + m0 + fr + 8, acc[mt][nq][3]);
        }
    }
}

// ---------------- plain-A GEMM (A via cp.async), RED output ------------------
__device__ __noinline__ void gemm_red(
    const float* __restrict__ A, const float* __restrict__ W,
    int ldw, int kc, float* __restrict__ outAcc, int m_eff,
    float* sA, float* sW, int tid)
{
    const int lane = tid & 31;
    const int wid  = tid >> 5;
    const int wm = wid & 1, wn = wid >> 1;
    const int fr = lane >> 2, fc = lane & 3;
    const int r  = tid >> 4;
    const int c4 = (tid & 15) << 2;
    const unsigned la0 = (unsigned)((r*SST + c4) * 4);
    const unsigned la1 = (unsigned)(((r+16)*SST + c4) * 4);
    const unsigned aB = (unsigned)__cvta_generic_to_shared(sA);
    const unsigned wB = (unsigned)__cvta_generic_to_shared(sW);
    const int nslab = kc >> 5;
    const bool live0 = (wm*32)      < m_eff;
    const bool live1 = (wm*32 + 16) < m_eff;

    float acc[2][2][4];
#pragma unroll
    for (int i = 0; i < 2; i++)
#pragma unroll
        for (int j = 0; j < 2; j++)
#pragma unroll
            for (int q = 0; q < 4; q++) acc[i][j][q] = 0.f;

    {
        const float* a = A + r*64 + c4;
        const float* w = W + (size_t)r*ldw + c4;
        CP_ASYNC16(aB + la0, a);
        CP_ASYNC16(aB + la1, a + 16*64);
        CP_ASYNC16(wB + la0, w);
        CP_ASYNC16(wB + la1, w + (size_t)16*ldw);
        CP_COMMIT;
    }
    for (int s = 0; s < nslab; s++){
        const int cur = (s & 1) ? KSLAB*SST : 0;
        if (s + 1 < nslab){
            const unsigned nxt = ((s+1) & 1) ? (unsigned)(KSLAB*SST*4) : 0u;
            const float* a = A + (size_t)((s+1)*KSLAB + r)*64 + c4;
            const float* w = W + (size_t)((s+1)*KSLAB + r)*ldw + c4;
            CP_ASYNC16(aB + nxt + la0, a);
            CP_ASYNC16(aB + nxt + la1, a + 16*64);
            CP_ASYNC16(wB + nxt + la0, w);
            CP_ASYNC16(wB + nxt + la1, w + (size_t)16*ldw);
            CP_COMMIT;
            CP_WAIT(1);
        } else { CP_WAIT(0); }
        __syncthreads();
        mma_body(acc, sA, sW, cur, wm, wn, fr, fc, live0, live1);
        __syncthreads();
    }
    red_epilogue(acc, outAcc, wm, wn, fr, fc, m_eff);
}

// ---------------- math-A GEMM: A = tf32r(relu(acc (+xe) + bias[k])) ----------
template<bool HASXE>
__device__ __noinline__ void gemm_red_mA(
    const float* __restrict__ accP, const float* __restrict__ xe,
    const float* __restrict__ bias,
    const float* __restrict__ W, int ldw, int kc,
    float* __restrict__ outAcc, int m_eff,
    float* sA, float* sW, int tid)
{
    const int lane = tid & 31;
    const int wid  = tid >> 5;
    const int wm = wid & 1, wn = wid >> 1;
    const int fr = lane >> 2, fc = lane & 3;
    const int r  = tid >> 4;
    const int c4 = (tid & 15) << 2;
    const unsigned la0 = (unsigned)((r*SST + c4) * 4);
    const unsigned la1 = (unsigned)(((r+16)*SST + c4) * 4);
    const unsigned wB = (unsigned)__cvta_generic_to_shared(sW);
    const int nslab = kc >> 5;
    const bool live0 = (wm*32)      < m_eff;
    const bool live1 = (wm*32 + 16) < m_eff;

    float acc[2][2][4];
#pragma unroll
    for (int i = 0; i < 2; i++)
#pragma unroll
        for (int j = 0; j < 2; j++)
#pragma unroll
            for (int q = 0; q < 4; q++) acc[i][j][q] = 0.f;

    float4 a0, a1, x0, x1; float b0, b1;
    auto loadA = [&](int s){
        size_t base = (size_t)(s*KSLAB + r)*64 + c4;
        a0 = *(const float4*)(accP + base);
        a1 = *(const float4*)(accP + base + 16*64);
        if (HASXE){ x0 = *(const float4*)(xe + base);
                    x1 = *(const float4*)(xe + base + 16*64); }
        b0 = bias[s*KSLAB + r];
        b1 = bias[s*KSLAB + r + 16];
    };
    auto stsA = [&](int s){
        float* dst = sA + ((s & 1) ? KSLAB*SST : 0);
        float4 v0, v1;
        v0.x = tf32r(fmaxf(a0.x + (HASXE ? x0.x : 0.f) + b0, 0.f));
        v0.y = tf32r(fmaxf(a0.y + (HASXE ? x0.y : 0.f) + b0, 0.f));
        v0.z = tf32r(fmaxf(a0.z + (HASXE ? x0.z : 0.f) + b0, 0.f));
        v0.w = tf32r(fmaxf(a0.w + (HASXE ? x0.w : 0.f) + b0, 0.f));
        v1.x = tf32r(fmaxf(a1.x + (HASXE ? x1.x : 0.f) + b1, 0.f));
        v1.y = tf32r(fmaxf(a1.y + (HASXE ? x1.y : 0.f) + b1, 0.f));
        v1.z = tf32r(fmaxf(a1.z + (HASXE ? x1.z : 0.f) + b1, 0.f));
        v1.w = tf32r(fmaxf(a1.w + (HASXE ? x1.w : 0.f) + b1, 0.f));
        *(float4*)(dst + r*SST + c4)       = v0;
        *(float4*)(dst + (r+16)*SST + c4)  = v1;
    };
    auto cpW = [&](int s){
        const unsigned off = (s & 1) ? (unsigned)(KSLAB*SST*4) : 0u;
        const float* w = W + (size_t)(s*KSLAB + r)*ldw + c4;
        CP_ASYNC16(wB + off + la0, w);
        CP_ASYNC16(wB + off + la1, w + (size_t)16*ldw);
        CP_COMMIT;
    };

    loadA(0);
    cpW(0);
    for (int s = 0; s < nslab; s++){
        const int cur = (s & 1) ? KSLAB*SST : 0;
        stsA(s);
        if (s + 1 < nslab){
            cpW(s + 1);
            loadA(s + 1);
            CP_WAIT(1);
        } else { CP_WAIT(0); }
        __syncthreads();
        mma_body(acc, sA, sW, cur, wm, wn, fr, fc, live0, live1);
        __syncthreads();
    }
    red_epilogue(acc, outAcc, wm, wn, fr, fc, m_eff);
}

// ---------------- init A ------------------------------------------------------
__global__ void init_misc(const float* __restrict__ y0,
                          const float* __restrict__ y1,
                          const float* __restrict__ W_e_in,
                          const float* __restrict__ W_e_h,
                          const float* __restrict__ W_e_out,
                          const float* __restrict__ W_ih,
                          const float* __restrict__ W_hh,
                          const float* __restrict__ W_o_in,
                          const float* __restrict__ W_o_h,
                          const float* __restrict__ W_o_out){
    int i = blockIdx.x * blockDim.x + threadIdx.x;
    int n = gridDim.x * blockDim.x;
    if (i == 0) g_bar = 0u;
    for (int idx = i; idx < 2*HB; idx += n) g_rh[idx] = 0.f;
    for (int idx = i; idx < HB; idx += n){
        g_c[idx] = 0.f; g_hr[idx] = 0.f;
        g_accE2[idx] = 0.f; g_accE[idx] = 0.f;
        g_accD1[idx] = 0.f; g_accD2[idx] = 0.f; g_accE1[idx] = 0.f;
    }
    for (int idx = i; idx < 4*HB; idx += n) g_accG[idx] = 0.f;
    for (int idx = i; idx < OUTD*BB; idx += n){
        g_accY[idx] = 0.f;
        int j = idx >> 6, b = idx & 63;
        g_y2[idx]           = tf32r(y1[b*OUTD + j]);
        g_y2[OUTD*BB + idx] = tf32r(y0[b*OUTD + j]);
    }
    for (int idx = i; idx < HH*HH; idx += n){
        g_Weh[idx] = tf32r(W_e_h[idx]);
        g_Weo[idx] = tf32r(W_e_out[idx]);
        g_Woi[idx] = tf32r(W_o_in[idx]);
        g_Woh[idx] = tf32r(W_o_h[idx]);
    }
    for (int idx = i; idx < HH*OUTD; idx += n) g_Woo[idx] = tf32r(W_o_out[idx]);
    for (int idx = i; idx < 128*HH; idx += n)
        g_Wey[idx] = tf32r(W_e_in[(size_t)256*HH + idx]);
    for (int idx = i; idx < 1024*4096; idx += n){
        g_Wcat[idx]                     = tf32r(W_ih[idx]);
        g_Wcat[(size_t)1024*4096 + idx] = tf32r(W_hh[idx]);
    }
}

// ---------------- init B: xe[t] = x_t @ W_e_in[0:256]  (fp32 exact) ----------
__global__ void init_xe(const float* __restrict__ x,
                        const float* __restrict__ W_e_in){
    __shared__ __align__(16) float As[16*64];
    __shared__ __align__(16) float Ws[16*64];
    const int tid = threadIdx.x;
    const int t  = blockIdx.x >> 4;
    const int nt = blockIdx.x & 15;
    const int tx = tid & 15, ty = tid >> 4;

    float acc[4][4] = {{0,0,0,0},{0,0,0,0},{0,0,0,0},{0,0,0,0}};
    for (int kb = 0; kb < FIN_; kb += 16){
        {
            int m  = tid >> 2;
            int kq = (tid & 3) << 2;
            float4 v = *(const float4*)(x + ((size_t)m*TTT + t)*FIN_ + kb + kq);
            As[(kq+0)*64 + m] = v.x; As[(kq+1)*64 + m] = v.y;
            As[(kq+2)*64 + m] = v.z; As[(kq+3)*64 + m] = v.w;
        }
        {
            int k  = tid >> 4;
            int n4 = (tid & 15) << 2;
            *(float4*)&Ws[k*64 + n4] = *(const float4*)(W_e_in + (size_t)(kb + k)*HH + nt*64 + n4);
        }
        __syncthreads();
#pragma unroll
        for (int k = 0; k < 16; k++){
            float4 a = *(const float4*)&As[k*64 + (ty << 2)];
            float4 w = *(const float4*)&Ws[k*64 + (tx << 2)];
            acc[0][0] = fmaf(a.x, w.x, acc[0][0]); acc[0][1] = fmaf(a.x, w.y, acc[0][1]);
            acc[0][2] = fmaf(a.x, w.z, acc[0][2]); acc[0][3] = fmaf(a.x, w.w, acc[0][3]);
            acc[1][0] = fmaf(a.y, w.x, acc[1][0]); acc[1][1] = fmaf(a.y, w.y, acc[1][1]);
            acc[1][2] = fmaf(a.y, w.z, acc[1][2]); acc[1][3] = fmaf(a.y, w.w, acc[1][3]);
            acc[2][0] = fmaf(a.z, w.x, acc[2][0]); acc[2][1] = fmaf(a.z, w.y, acc[2][1]);
            acc[2][2] = fmaf(a.z, w.z, acc[2][2]); acc[2][3] = fmaf(a.z, w.w, acc[2][3]);
            acc[3][0] = fmaf(a.w, w.x, acc[3][0]); acc[3][1] = fmaf(a.w, w.y, acc[3][1]);
            acc[3][2] = fmaf(a.w, w.z, acc[3][2]); acc[3][3] = fmaf(a.w, w.w, acc[3][3]);
        }
        __syncthreads();
    }
    const int m0 = ty << 2;
#pragma unroll
    for (int j = 0; j < 4; j++){
        int ng = nt*64 + (tx << 2) + j;
        *(float4*)(g_xe + (size_t)t*HB + (size_t)ng*64 + m0) =
            make_float4(acc[0][j], acc[1][j], acc[2][j], acc[3][j]);
    }
}

// ---------------- init C: Wfused = Woo @ (Wey_y + Wey_yp); beff --------------
__global__ void init_wf(const float* __restrict__ W_e_in,
                        const float* __restrict__ W_o_out,
                        const float* __restrict__ b_e_in,
                        const float* __restrict__ b_o_out){
    const int kt = blockIdx.x >> 4;
    const int nt = blockIdx.x & 15;
    const int tid = threadIdx.x;
    const int kr = tid >> 2;
    const int n0 = (tid & 3) * 16;

    const int k = kt*64 + kr;
    float acc[16];
#pragma unroll
    for (int q = 0; q < 16; q++) acc[q] = 0.f;
    for (int j = 0; j < 64; j++){
        float woo = W_o_out[(size_t)k*OUTD + j];
        const float* wy = W_e_in + (size_t)(256 + j)*HH + nt*64 + n0;
        const float* wp = W_e_in + (size_t)(320 + j)*HH + nt*64 + n0;
#pragma unroll
        for (int q = 0; q < 16; q++)
            acc[q] = fmaf(woo, wy[q] + wp[q], acc[q]);
    }
#pragma unroll
    for (int q = 0; q < 16; q++)
        g_Wfused[(size_t)k*HH + nt*64 + n0 + q] = tf32r(acc[q]);

    if (kt == 0 && tid < 64){
        int nn = nt*64 + tid;
        float s = b_e_in[nn];
        for (int j = 0; j < 64; j++)
            s = fmaf(b_o_out[j],
                     W_e_in[(size_t)(256 + j)*HH + nn] + W_e_in[(size_t)(320 + j)*HH + nn], s);
        g_beff[nn] = s;
    }
}

// ---------------- persistent RNN kernel -------------------------------------
__global__ void __launch_bounds__(NTHR, 2)
rnn_kernel(const int* __restrict__ x_len,
           const float* __restrict__ b_e_in,  const float* __restrict__ b_e_h,
           const float* __restrict__ b_e_out,
           const float* __restrict__ b_ih,    const float* __restrict__ b_hh,
           const float* __restrict__ b_o_in,  const float* __restrict__ b_o_h,
           const float* __restrict__ b_o_out,
           float* __restrict__ out)
{
    __shared__ __align__(16) float sA[2*KSLAB*SST];   // 18KB
    __shared__ __align__(16) float sW[2*KSLAB*SST];   // 18KB
    __shared__ int s_meff[TTT];
    __shared__ int s_xlen[BB];

    const int tid  = threadIdx.x;
    const int bid  = blockIdx.x;
    const int gtid = bid * NTHR + tid;
    unsigned target = GRID;

    float* __restrict__ ys_out   = out;
    float* __restrict__ skip_out = out + (size_t)BB*TTT*OUTD;

    if (tid < BB) s_xlen[tid] = x_len[tid];
    __syncthreads();
    for (int t = tid; t < TTT; t += NTHR){
        int c = 0;
#pragma unroll
        for (int m = 0; m < BB; m++) c += (s_xlen[m] > t) ? 1 : 0;
        s_meff[t] = c;
    }
    __syncthreads();

    // ==== prologue: accE1 += [y1;y0]@Wey  (32 jobs, kc=64) ====
    if (bid < 32){
        int nt = bid & 15, ks = bid >> 4;
        gemm_red(g_y2 + (size_t)ks*64*BB, g_Wey + (size_t)(ks*64)*HH + nt*64,
                 HH, 64, g_accE1 + (size_t)nt*4096, 64, sA, sW, tid);
    }
    grid_barrier(tid, target);

    for (int t = 0; t < TTT; t++){
        const int me = s_meff[t];

        // ---- P1: e1 = f(accE1 + xe[t] + bias) staged; @ W_e_h -> RED accE2.
        //          16nt x 16ks, kc=64, all CTAs.
        {
            int nt = bid & 15, ks = bid >> 4;
            const float* bias = (t == 0) ? b_e_in : g_beff;
            gemm_red_mA<true>(g_accE1 + (size_t)ks*64*64,
                              g_xe + (size_t)t*HB + (size_t)ks*64*64,
                              bias + ks*64,
                              g_Weh + (size_t)(ks*64)*HH + nt*64, HH, 64,
                              g_accE2 + (size_t)nt*4096, me, sA, sW, tid);
        }
        grid_barrier(tid, target);

        // ---- P3: e2 = f(accE2 + b_e_h) staged; @ W_e_out -> RED accE.
        //          Post-arrive: zero accE1 (consumed P11, 4 bars later);
        //                       y-store + zero accY (accY REDed in P11).
        {
            int nt = bid & 15, ks = bid >> 4;
            gemm_red_mA<false>(g_accE2 + (size_t)ks*64*64, (const float*)0,
                               b_e_h + ks*64,
                               g_Weo + (size_t)(ks*64)*HH + nt*64, HH, 64,
                               g_accE + (size_t)nt*4096, me, sA, sW, tid);
        }
        bar_arrive(tid);
        for (int idx = gtid*4; idx < HB; idx += GRID*NTHR*4)
            *(float4*)(g_accE1 + idx) = make_float4(0.f,0.f,0.f,0.f);
        if (t > 0){
            const int mep = s_meff[t-1];
            for (int idx = gtid; idx < OUTD*BB; idx += GRID*NTHR){
                float yv = g_accY[idx] + b_o_out[idx >> 6];
                int nn = idx >> 6, m = idx & 63;
                ys_out[((size_t)m*TTT + (t-1))*OUTD + nn] = (m < mep) ? yv : 0.f;
                g_accY[idx] = 0.f;
            }
        }
        bar_wait(tid, target);

        // ---- P5: gates = [r;h] @ W_cat (64nt x 4ks, kc=512) -> RED accG.
        //          ks<2: r = f(accE + b_e_out) staged; ks>=2: h from g_rh.
        //          Post-arrive: zero accE2 (consumed P1 next step, 3 bars).
        {
            int nt = bid & 63, ks = bid >> 6;
            if (ks < 2)
                gemm_red_mA<false>(g_accE + (size_t)ks*512*64, (const float*)0,
                                   b_e_out + ks*512,
                                   g_Wcat + (size_t)(ks*512)*4096 + nt*64, 4096, 512,
                                   g_accG + (size_t)nt*4096, me, sA, sW, tid);
            else
                gemm_red(g_rh + (size_t)ks*512*BB,
                         g_Wcat + (size_t)(ks*512)*4096 + nt*64, 4096, 512,
                         g_accG + (size_t)nt*4096, me, sA, sW, tid);
        }
        bar_arrive(tid);
        for (int idx = gtid*4; idx < HB; idx += GRID*NTHR*4)
            *(float4*)(g_accE2 + idx) = make_float4(0.f,0.f,0.f,0.f);
        bar_wait(tid, target);

        // ---- P6: LSTM pointwise + accD1 zero (pre-arrive; P7 REDs accD1);
        //          skip store + accE/accG/accD2 zero post-arrive
        //          (consumers >= 2 barriers downstream).
        for (int idx = gtid; idx < HB; idx += GRID*NTHR){
            int j = idx >> 6, m = idx & 63;
            size_t o0 = (size_t)j*64 + m;
            float ig = g_accG[o0              ] + b_ih[j     ] + b_hh[j     ];
            float fg = g_accG[o0 +     (size_t)HB] + b_ih[j+1024] + b_hh[j+1024];
            float gg = g_accG[o0 + 2*(size_t)HB] + b_ih[j+2048] + b_hh[j+2048];
            float og = g_accG[o0 + 3*(size_t)HB] + b_ih[j+3072] + b_hh[j+3072];
            float cn = sigm(fg)*g_c[idx] + sigm(ig)*tanhf(gg);
            float hn = sigm(og)*tanhf(cn);
            g_c[idx] = cn;
            float ht = tf32r(hn);
            g_rh[HB + idx] = ht;
            g_hr[idx]      = fmaxf(ht, 0.f);
            g_accD1[idx]   = 0.f;
        }
        bar_arrive(tid);
        for (int idx = gtid; idx < HB; idx += GRID*NTHR){
            int j = idx >> 6, m = idx & 63;
            float e = g_accE[idx] + b_e_out[j];
            skip_out[((size_t)m*TTT + t)*HH + j] = (m < me) ? e : 0.f;
            g_accE[idx]  = 0.f;             // consumed P3 next step (4 bars)
            g_accD2[idx] = 0.f;             // consumed P9 (2 bars)
            size_t o0 = (size_t)j*64 + m;
            g_accG[o0              ] = 0.f; // consumed P5 next step (5 bars)
            g_accG[o0 +     (size_t)HB] = 0.f;
            g_accG[o0 + 2*(size_t)HB] = 0.f;
            g_accG[o0 + 3*(size_t)HB] = 0.f;
        }
        bar_wait(tid, target);

        // ---- P7: d1 = relu(h) @ W_o_in -> RED accD1.  16nt x 16ks, kc=64.
        {
            int nt = bid & 15, ks = bid >> 4;
            gemm_red(g_hr + (size_t)ks*64*BB,
                     g_Woi + (size_t)(ks*64)*HH + nt*64, HH, 64,
                     g_accD1 + (size_t)nt*4096, me, sA, sW, tid);
        }
        grid_barrier(tid, target);

        // ---- P9: d1 = f(accD1 + b_o_in) staged; @ W_o_h -> RED accD2.
        {
            int nt = bid & 15, ks = bid >> 4;
            gemm_red_mA<false>(g_accD1 + (size_t)ks*64*64, (const float*)0,
                               b_o_in + ks*64,
                               g_Woh + (size_t)(ks*64)*HH + nt*64, HH, 64,
                               g_accD2 + (size_t)nt*4096, me, sA, sW, tid);
        }
        grid_barrier(tid, target);

        // ---- P11: d2 = f(accD2 + b_o_h) staged;
        //           bid<128: @ Wfused (kc=128, 8ks) -> RED accE1
        //           bid 128-143: @ Woo (kc=64, 16ks) -> RED accY
        if (bid < 128){
            int nt = bid & 15, ks = bid >> 4;
            gemm_red_mA<false>(g_accD2 + (size_t)ks*128*64, (const float*)0,
                               b_o_h + ks*128,
                               g_Wfused + (size_t)(ks*128)*HH + nt*64, HH, 128,
                               g_accE1 + (size_t)nt*4096, me, sA, sW, tid);
        } else if (bid < 144){
            int ks = bid - 128;
            gemm_red_mA<false>(g_accD2 + (size_t)ks*64*64, (const float*)0,
                               b_o_h + ks*64,
                               g_Woo + (size_t)(ks*64)*OUTD, OUTD, 64,
                               g_accY, me, sA, sW, tid);
        }
        grid_barrier(tid, target);
    }

    // ==== epilogue: store y(T-1) ====
    {
        const int mep = s_meff[TTT-1];
        for (int idx = gtid; idx < OUTD*BB; idx += GRID*NTHR){
            float yv = g_accY[idx] + b_o_out[idx >> 6];
            int nn = idx >> 6, m = idx & 63;
            ys_out[((size_t)m*TTT + (TTT-1))*OUTD + nn] = (m < mep) ? yv : 0.f;
        }
    }
}

// ---------------- launch -----------------------------------------------------
extern "C" void kernel_launch(void* const* d_in, const int* in_sizes, int n_in,
                              void* d_out, int out_size)
{
    (void)in_sizes; (void)n_in; (void)out_size;
    const float* x       = (const float*)d_in[0];
    const int*   x_len   = (const int*)  d_in[1];
    const float* y_0     = (const float*)d_in[2];
    const float* y_1     = (const float*)d_in[3];
    const float* W_e_in  = (const float*)d_in[4];
    const float* b_e_in  = (const float*)d_in[5];
    const float* W_e_h   = (const float*)d_in[6];
    const float* b_e_h   = (const float*)d_in[7];
    const float* W_e_out = (const float*)d_in[8];
    const float* b_e_out = (const float*)d_in[9];
    const float* W_ih    = (const float*)d_in[10];
    const float* W_hh    = (const float*)d_in[11];
    const float* b_ih    = (const float*)d_in[12];
    const float* b_hh    = (const float*)d_in[13];
    const float* W_o_in  = (const float*)d_in[14];
    const float* b_o_in  = (const float*)d_in[15];
    const float* W_o_h   = (const float*)d_in[16];
    const float* b_o_h   = (const float*)d_in[17];
    const float* W_o_out = (const float*)d_in[18];
    const float* b_o_out = (const float*)d_in[19];

    init_misc<<<1024, 256>>>(y_0, y_1, W_e_in, W_e_h, W_e_out,
                             W_ih, W_hh, W_o_in, W_o_h, W_o_out);
    init_xe<<<TTT*16, 256>>>(x, W_e_in);
    init_wf<<<256, 256>>>(W_e_in, W_o_out, b_e_in, b_o_out);
    rnn_kernel<<<GRID, NTHR>>>(x_len,
                               b_e_in, b_e_h, b_e_out,
                               b_ih, b_hh,
                               b_o_in, b_o_h, b_o_out,
                               (float*)d_out);
}